// round 4
// baseline (speedup 1.0000x reference)
#include <cuda_runtime.h>
#include <math.h>

#define RANGE_MIN (-5.0f)
#define RANGE_MAX (5.0f)
#define MIN_BIN_SIZE 0.0001f
#define MIN_SLOPE 0.0001f
#define KBINS 8
#define NCELLS 1024

// Bin table, stride 12 floats (48B) => conflict-free LDS.128 across 8 bins.
// [b*12 + 0..7]: nxkw(=-x_k*inv_w), inv_w, y_k, h, s, c(=dk+dk1-2s), d_k, d_k1
__device__ __align__(16) float g_tab[96];
// Cell table: .x = deciding knot (1e30 if none), .y = bitcast(int byte_offset b*48)
__device__ __align__(16) float2 g_cells[NCELLS];

__global__ void rqs_prep_kernel(const float* __restrict__ p) {
    if (threadIdx.x != 0 || blockIdx.x != 0) return;

    float w[KBINS], h[KBINS], d[KBINS + 1];
    float mw = -1e30f, mh = -1e30f;
    for (int i = 0; i < KBINS; i++) {
        mw = fmaxf(mw, p[i]);
        mh = fmaxf(mh, p[KBINS + i]);
    }
    float sw = 0.f, sh = 0.f;
    for (int i = 0; i < KBINS; i++) {
        w[i] = expf(p[i] - mw);         sw += w[i];
        h[i] = expf(p[KBINS + i] - mh); sh += h[i];
    }
    const float total = RANGE_MAX - RANGE_MIN;
    const float scale = total - KBINS * MIN_BIN_SIZE;
    for (int i = 0; i < KBINS; i++) {
        w[i] = w[i] / sw * scale + MIN_BIN_SIZE;
        h[i] = h[i] / sh * scale + MIN_BIN_SIZE;
    }
    const float off = logf(expf(1.0f - MIN_SLOPE) - 1.0f);
    for (int i = 0; i <= KBINS; i++) {
        float z = p[2 * KBINS + i] + off;
        d[i] = ((z > 20.f) ? z : log1pf(expf(z))) + MIN_SLOPE;
    }
    float xp[KBINS + 1], yp[KBINS + 1];
    xp[0] = RANGE_MIN; yp[0] = RANGE_MIN;
    float cx = 0.f, cy = 0.f;
    for (int i = 0; i < KBINS; i++) {
        cx += w[i]; xp[i + 1] = RANGE_MIN + cx;
        cy += h[i]; yp[i + 1] = RANGE_MIN + cy;
    }
    for (int i = 0; i < 96; i++) g_tab[i] = 0.f;
    for (int b = 0; b < KBINS; b++) {
        float wid   = xp[b + 1] - xp[b];
        float hei   = yp[b + 1] - yp[b];
        float inv_w = 1.0f / wid;
        float s     = hei / wid;
        g_tab[b * 12 + 0] = -xp[b] * inv_w;
        g_tab[b * 12 + 1] = inv_w;
        g_tab[b * 12 + 2] = yp[b];
        g_tab[b * 12 + 3] = hei;
        g_tab[b * 12 + 4] = s;
        g_tab[b * 12 + 5] = d[b + 1] + d[b] - 2.0f * s;
        g_tab[b * 12 + 6] = d[b];
        g_tab[b * 12 + 7] = d[b + 1];
    }
    // Cell table: for cell c with left edge L, base bin = #{interior knots <= L};
    // at most one knot crossing inside a cell => bin = base + (xc >= next_knot).
    const double delta = (double)(RANGE_MAX - RANGE_MIN) / NCELLS;
    for (int c = 0; c < NCELLS; c++) {
        float L = (float)(RANGE_MIN + c * delta);
        int b = 0;
        for (int j = 1; j <= 7; j++) b += (xp[j] <= L) ? 1 : 0;
        float knot = (b < 7) ? xp[b + 1] : 1e30f;
        float2 ce;
        ce.x = knot;
        ce.y = __int_as_float(b * 48);
        g_cells[c] = ce;
    }
}

__device__ __forceinline__ void rqs_eval(float xx,
                                         const float* __restrict__ stab,
                                         const float2* __restrict__ scell,
                                         float& y_out, float& ld_out) {
    float xc = fminf(fmaxf(xx, RANGE_MIN), RANGE_MAX);

    // cell index: floor((xc - RANGE_MIN) * NCELLS/10), clamped to NCELLS-1
    const float invD = (float)NCELLS / (RANGE_MAX - RANGE_MIN);
    float cf = fminf(fmaf(xc, invD, -RANGE_MIN * invD), (float)(NCELLS - 1));
    int ci = (int)cf;  // cf >= -eps truncates to 0

    float2 ce = scell[ci];
    int boff = __float_as_int(ce.y) + ((xc >= ce.x) ? 48 : 0);

    const float* bp = (const float*)((const char*)stab + boff);
    const float4 lo = *reinterpret_cast<const float4*>(bp);      // nxkw, inv_w, y_k, h
    const float4 hi = *reinterpret_cast<const float4*>(bp + 4);  // s, c, d_k, d_k1

    float xi   = fmaf(xc, lo.y, lo.x);
    float omxi = 1.0f - xi;
    float xom  = xi * omxi;

    float s = hi.x, cc = hi.y, dk = hi.z, dk1 = hi.w;
    float num = fmaf(s * xi, xi, dk * xom);
    float den = fmaf(cc, xom, s);
    float r   = __fdividef(1.0f, den);

    float y = fmaf(lo.w * num, r, lo.z);
    // linear tail: below range uses d0 (= dk of bin 0), above uses d8 (= dk1 of bin 7)
    float edge = (xx < 0.0f) ? dk : dk1;
    y = fmaf(xx - xc, edge, y);

    float t4    = fmaf(s + s, xom, (dk * omxi) * omxi);
    float inner = fmaf(dk1 * xi, xi, t4);
    float srr   = s * r;
    ld_out = __logf(srr * srr * inner);   // equals log(edge slope) at clamped bounds
    y_out  = y;
}

__global__ void __launch_bounds__(256, 6) rqs_main_kernel(
    const float4* __restrict__ x4,
    float4* __restrict__ y4,
    float4* __restrict__ ld4
) {
    __shared__ __align__(16) float  stab[96];
    __shared__ __align__(16) float2 scell[NCELLS];
    if (threadIdx.x < 96) stab[threadIdx.x] = g_tab[threadIdx.x];
#pragma unroll
    for (int t = threadIdx.x; t < NCELLS; t += 256) scell[t] = g_cells[t];
    __syncthreads();

    int i0 = blockIdx.x * 512 + threadIdx.x;
#pragma unroll
    for (int u = 0; u < 2; u++) {
        int i = i0 + u * 256;
        float4 xv = __ldcs(&x4[i]);
        float4 yv, lv;
        rqs_eval(xv.x, stab, scell, yv.x, lv.x);
        rqs_eval(xv.y, stab, scell, yv.y, lv.y);
        rqs_eval(xv.z, stab, scell, yv.z, lv.z);
        rqs_eval(xv.w, stab, scell, yv.w, lv.w);
        __stcs(&y4[i],  yv);
        __stcs(&ld4[i], lv);
    }
}

// Tail: handles elements [start, n) scalar-wise (not launched when n % 2048 == 0)
__global__ void rqs_tail_kernel(const float* __restrict__ x,
                                float* __restrict__ y,
                                float* __restrict__ ld,
                                int start, int n) {
    __shared__ __align__(16) float  stab[96];
    __shared__ __align__(16) float2 scell[NCELLS];
    if (threadIdx.x < 96) stab[threadIdx.x] = g_tab[threadIdx.x];
    for (int t = threadIdx.x; t < NCELLS; t += blockDim.x) scell[t] = g_cells[t];
    __syncthreads();
    for (int idx = start + blockIdx.x * blockDim.x + threadIdx.x; idx < n;
         idx += gridDim.x * blockDim.x) {
        float yy, ll;
        rqs_eval(x[idx], stab, scell, yy, ll);
        y[idx]  = yy;
        ld[idx] = ll;
    }
}

extern "C" void kernel_launch(void* const* d_in, const int* in_sizes, int n_in,
                              void* d_out, int out_size) {
    const float* x = (const float*)d_in[0];
    const float* p = (const float*)d_in[1];
    float* out = (float*)d_out;
    const int n = in_sizes[0];

    float* y_ptr  = out;       // out[0:N]  = y
    float* ld_ptr = out + n;   // out[N:2N] = logdet

    rqs_prep_kernel<<<1, 32>>>(p);

    const int elems_per_block = 2048;            // 256 thr * 2 * float4
    const int full_blocks = n / elems_per_block; // exact tiles, no bounds checks
    if (full_blocks > 0) {
        rqs_main_kernel<<<full_blocks, 256>>>(
            (const float4*)x, (float4*)y_ptr, (float4*)ld_ptr);
    }
    const int done = full_blocks * elems_per_block;
    if (done < n) {
        rqs_tail_kernel<<<2, 256>>>(x, y_ptr, ld_ptr, done, n);
    }
}

// round 5
// speedup vs baseline: 3.1267x; 3.1267x over previous
#include <cuda_runtime.h>
#include <math.h>

#define RANGE_MIN (-5.0f)
#define RANGE_MAX (5.0f)
#define MIN_BIN_SIZE 0.0001f
#define MIN_SLOPE 0.0001f
#define KBINS 8

// Bin table, stride 12 floats (48B) => conflict-free LDS.128 across 8 bins:
//   bank group of bin b = (b*12)%32 = {0,12,24,4,16,28,8,20} — all disjoint.
// [b*12 + 0..7]: nxkw(=-x_k*inv_w), inv_w, y_k, h, s, c(=dk+dk1-2s), d_k, d_k1
// [96..102]: interior knots x_pos[1..7]
__device__ __align__(16) float g_tab[112];

__global__ void rqs_prep_kernel(const float* __restrict__ p) {
    if (threadIdx.x != 0 || blockIdx.x != 0) return;

    float w[KBINS], h[KBINS], d[KBINS + 1];
    float mw = -1e30f, mh = -1e30f;
    for (int i = 0; i < KBINS; i++) {
        mw = fmaxf(mw, p[i]);
        mh = fmaxf(mh, p[KBINS + i]);
    }
    float sw = 0.f, sh = 0.f;
    for (int i = 0; i < KBINS; i++) {
        w[i] = expf(p[i] - mw);         sw += w[i];
        h[i] = expf(p[KBINS + i] - mh); sh += h[i];
    }
    const float total = RANGE_MAX - RANGE_MIN;
    const float scale = total - KBINS * MIN_BIN_SIZE;
    for (int i = 0; i < KBINS; i++) {
        w[i] = w[i] / sw * scale + MIN_BIN_SIZE;
        h[i] = h[i] / sh * scale + MIN_BIN_SIZE;
    }
    const float off = logf(expf(1.0f - MIN_SLOPE) - 1.0f);
    for (int i = 0; i <= KBINS; i++) {
        float z = p[2 * KBINS + i] + off;
        d[i] = ((z > 20.f) ? z : log1pf(expf(z))) + MIN_SLOPE;
    }
    float xp[KBINS + 1], yp[KBINS + 1];
    xp[0] = RANGE_MIN; yp[0] = RANGE_MIN;
    float cx = 0.f, cy = 0.f;
    for (int i = 0; i < KBINS; i++) {
        cx += w[i]; xp[i + 1] = RANGE_MIN + cx;
        cy += h[i]; yp[i + 1] = RANGE_MIN + cy;
    }
    for (int i = 0; i < 112; i++) g_tab[i] = 0.f;
    for (int b = 0; b < KBINS; b++) {
        float wid   = xp[b + 1] - xp[b];
        float hei   = yp[b + 1] - yp[b];
        float inv_w = 1.0f / wid;
        float s     = hei / wid;
        g_tab[b * 12 + 0] = -xp[b] * inv_w;
        g_tab[b * 12 + 1] = inv_w;
        g_tab[b * 12 + 2] = yp[b];
        g_tab[b * 12 + 3] = hei;
        g_tab[b * 12 + 4] = s;
        g_tab[b * 12 + 5] = d[b + 1] + d[b] - 2.0f * s;
        g_tab[b * 12 + 6] = d[b];
        g_tab[b * 12 + 7] = d[b + 1];
    }
    for (int i = 0; i < 7; i++) g_tab[96 + i] = xp[1 + i];
}

__device__ __forceinline__ void rqs_eval(float xx, const float* __restrict__ stab,
                                         float k1, float k2, float k3, float k4,
                                         float k5, float k6, float k7,
                                         float& y_out, float& ld_out) {
    float xc = fminf(fmaxf(xx, RANGE_MIN), RANGE_MAX);

    // binary searchsorted over 7 interior knots (side='right')
    bool  c2  = xc >= k4;
    float km1 = c2 ? k6 : k2;
    bool  c1  = xc >= km1;
    float kmA = c2 ? k7 : k3;
    float kmB = c2 ? k5 : k1;
    float km0 = c1 ? kmA : kmB;
    bool  c0  = xc >= km0;
    int boff = (c2 ? 192 : 0) + (c1 ? 96 : 0) + (c0 ? 48 : 0);

    const float* bp = (const float*)((const char*)stab + boff);
    const float4 lo = *reinterpret_cast<const float4*>(bp);      // nxkw, inv_w, y_k, h
    const float4 hi = *reinterpret_cast<const float4*>(bp + 4);  // s, c, d_k, d_k1

    float xi   = fmaf(xc, lo.y, lo.x);
    float omxi = 1.0f - xi;
    float xom  = xi * omxi;

    float s = hi.x, cc = hi.y, dk = hi.z, dk1 = hi.w;
    float num = fmaf(s * xi, xi, dk * xom);
    float den = fmaf(cc, xom, s);
    float r   = __fdividef(1.0f, den);

    float y = fmaf(lo.w * num, r, lo.z);
    // linear tail: below range uses d0 (= dk of bin 0), above uses d8 (= dk1 of bin 7);
    // (xx - xc) == 0 for in-range, so the select value is irrelevant there.
    float edge = (xx < 0.0f) ? dk : dk1;
    y = fmaf(xx - xc, edge, y);

    float t4    = fmaf(s + s, xom, (dk * omxi) * omxi);
    float inner = fmaf(dk1 * xi, xi, t4);
    float srr   = s * r;
    ld_out = __logf(srr * srr * inner);   // == log(edge slope) at clamped bounds
    y_out  = y;
}

// Each thread: 4 float4 loads issued UP-FRONT (MLP=4), then compute+store.
__global__ void __launch_bounds__(256, 5) rqs_main_kernel(
    const float4* __restrict__ x4,
    float4* __restrict__ y4,
    float4* __restrict__ ld4
) {
    __shared__ __align__(16) float stab[112];
    if (threadIdx.x < 112) stab[threadIdx.x] = g_tab[threadIdx.x];
    __syncthreads();

    const float k1 = stab[96],  k2 = stab[97],  k3 = stab[98],  k4 = stab[99];
    const float k5 = stab[100], k6 = stab[101], k7 = stab[102];

    int i0 = blockIdx.x * 1024 + threadIdx.x;

    // batch all loads first — 4 outstanding LDG.128 per thread
    float4 xv0 = __ldcs(&x4[i0]);
    float4 xv1 = __ldcs(&x4[i0 + 256]);
    float4 xv2 = __ldcs(&x4[i0 + 512]);
    float4 xv3 = __ldcs(&x4[i0 + 768]);

    float4 yv, lv;

    rqs_eval(xv0.x, stab, k1,k2,k3,k4,k5,k6,k7, yv.x, lv.x);
    rqs_eval(xv0.y, stab, k1,k2,k3,k4,k5,k6,k7, yv.y, lv.y);
    rqs_eval(xv0.z, stab, k1,k2,k3,k4,k5,k6,k7, yv.z, lv.z);
    rqs_eval(xv0.w, stab, k1,k2,k3,k4,k5,k6,k7, yv.w, lv.w);
    __stcs(&y4[i0],  yv);
    __stcs(&ld4[i0], lv);

    rqs_eval(xv1.x, stab, k1,k2,k3,k4,k5,k6,k7, yv.x, lv.x);
    rqs_eval(xv1.y, stab, k1,k2,k3,k4,k5,k6,k7, yv.y, lv.y);
    rqs_eval(xv1.z, stab, k1,k2,k3,k4,k5,k6,k7, yv.z, lv.z);
    rqs_eval(xv1.w, stab, k1,k2,k3,k4,k5,k6,k7, yv.w, lv.w);
    __stcs(&y4[i0 + 256],  yv);
    __stcs(&ld4[i0 + 256], lv);

    rqs_eval(xv2.x, stab, k1,k2,k3,k4,k5,k6,k7, yv.x, lv.x);
    rqs_eval(xv2.y, stab, k1,k2,k3,k4,k5,k6,k7, yv.y, lv.y);
    rqs_eval(xv2.z, stab, k1,k2,k3,k4,k5,k6,k7, yv.z, lv.z);
    rqs_eval(xv2.w, stab, k1,k2,k3,k4,k5,k6,k7, yv.w, lv.w);
    __stcs(&y4[i0 + 512],  yv);
    __stcs(&ld4[i0 + 512], lv);

    rqs_eval(xv3.x, stab, k1,k2,k3,k4,k5,k6,k7, yv.x, lv.x);
    rqs_eval(xv3.y, stab, k1,k2,k3,k4,k5,k6,k7, yv.y, lv.y);
    rqs_eval(xv3.z, stab, k1,k2,k3,k4,k5,k6,k7, yv.z, lv.z);
    rqs_eval(xv3.w, stab, k1,k2,k3,k4,k5,k6,k7, yv.w, lv.w);
    __stcs(&y4[i0 + 768],  yv);
    __stcs(&ld4[i0 + 768], lv);
}

// Tail: handles [start, n) scalar-wise (not launched when n % 4096 == 0)
__global__ void rqs_tail_kernel(const float* __restrict__ x,
                                float* __restrict__ y,
                                float* __restrict__ ld,
                                int start, int n) {
    __shared__ __align__(16) float stab[112];
    if (threadIdx.x < 112) stab[threadIdx.x] = g_tab[threadIdx.x];
    __syncthreads();
    for (int idx = start + blockIdx.x * blockDim.x + threadIdx.x; idx < n;
         idx += gridDim.x * blockDim.x) {
        float yy, ll;
        rqs_eval(x[idx], stab,
                 stab[96], stab[97], stab[98], stab[99],
                 stab[100], stab[101], stab[102], yy, ll);
        y[idx]  = yy;
        ld[idx] = ll;
    }
}

extern "C" void kernel_launch(void* const* d_in, const int* in_sizes, int n_in,
                              void* d_out, int out_size) {
    const float* x = (const float*)d_in[0];
    const float* p = (const float*)d_in[1];
    float* out = (float*)d_out;
    const int n = in_sizes[0];

    float* y_ptr  = out;       // out[0:N]  = y
    float* ld_ptr = out + n;   // out[N:2N] = logdet

    rqs_prep_kernel<<<1, 32>>>(p);

    const int elems_per_block = 4096;            // 256 thr * 4 * float4
    const int full_blocks = n / elems_per_block; // exact tiles, no bounds checks
    if (full_blocks > 0) {
        rqs_main_kernel<<<full_blocks, 256>>>(
            (const float4*)x, (float4*)y_ptr, (float4*)ld_ptr);
    }
    const int done = full_blocks * elems_per_block;
    if (done < n) {
        rqs_tail_kernel<<<4, 256>>>(x, y_ptr, ld_ptr, done, n);
    }
}